// round 7
// baseline (speedup 1.0000x reference)
#include <cuda_runtime.h>
#include <math.h>

#define NNODE 856
#define NEDGE 2896
#define NSEQ  1696
#define NHF   128
#define NNF_  17
#define DM    160
#define SEQL  107
#define NLAY  10
#define WCN   1408
#define EPSF  1e-5f
#define NB    444
#define NT    256
#define NTH   (NB*NT)
#define BK    32

// ---------------- device scratch ----------------
__device__ float g_dinv[NNODE];
__device__ int   g_degi[NNODE];
__device__ float g_tx1[NNODE * NNF_];
__device__ float g_tx2[NNODE * NNF_];
__device__ float g_h[NNODE * NHF];
__device__ float g_hin[NNODE * NHF];
__device__ float g_Bm[NLAY * 320];
__device__ float g_Wc[NLAY * NHF * WCN];
__device__ float g_P[NNODE * WCN];
__device__ int   g_cnti[NNODE];
__device__ int   g_rp[NNODE + 1];
__device__ int   g_eid[NEDGE];
__device__ float g_t[NNODE * DM];
__device__ float g_qkv[NNODE * 480];
__device__ float g_att[NNODE * DM];
__device__ unsigned g_barcnt;
__device__ volatile unsigned g_bargen;

// ---------------- grid barrier: CG-style, thread-0 fences only ----------------
__device__ __forceinline__ void gbar() {
    __syncthreads();
    if (threadIdx.x == 0) {
        __threadfence();                   // release (bar.sync cumulativity covers block)
        unsigned gen = g_bargen;
        if (atomicAdd(&g_barcnt, 1u) == NB - 1u) {
            g_barcnt = 0u;
            __threadfence();
            g_bargen = gen + 1u;
        } else {
            while (g_bargen == gen) __nanosleep(64);
        }
        __threadfence();                   // acquire
    }
    __syncthreads();
}

__device__ __forceinline__ float geluf(float x) {
    return 0.5f * x * (1.0f + erff(x * 0.70710678118654752f));
}

// guarded float4 B-tile load: row always valid, col may exceed N
__device__ __forceinline__ float4 ldB4(const float* __restrict__ B, int row,
                                       int col, int N) {
    if (col + 3 < N) return *(const float4*)&B[row * N + col];
    float4 r = make_float4(0.f, 0.f, 0.f, 0.f);
    if (col     < N) r.x = B[row * N + col];
    if (col + 1 < N) r.y = B[row * N + col + 1];
    if (col + 2 < N) r.z = B[row * N + col + 2];
    return r;
}

// ---------------- tiled GEMM phase: C = act(A@B + bias) ----------------
// 64x64 tile, BK=32, register-staged pipeline, packed f32x2 FMA. K % 32 == 0.
__device__ void gemm_tiles(const float* __restrict__ A, const float* __restrict__ B,
                           const float* __restrict__ bias, float* __restrict__ C,
                           int M, int N, int K, int act, float* SB) {
    float* As = SB;              // [BK][68] padded
    float* Bs = SB + BK * 68;    // [BK][64]
    const int ntc = (N + 63) >> 6;
    const int ntiles = ((M + 63) >> 6) * ntc;
    const int tid = threadIdx.x;
    const int tx = tid & 15, ty = tid >> 4;
    const int arow = tid >> 3;
    const int ac   = (tid & 7) * 4;
    const int bk   = tid >> 4;
    const int bc   = (tid & 15) * 4;

    for (int t = blockIdx.x; t < ntiles; t += NB) {
        int tr = t / ntc;
        int rb = tr * 64, cb = (t - tr * ntc) * 64;
        unsigned long long accp[4][2];
#pragma unroll
        for (int i = 0; i < 4; i++) { accp[i][0] = 0ull; accp[i][1] = 0ull; }

        float ar[2][4];
        float4 br[2];
#pragma unroll
        for (int u = 0; u < 2; u++) {
            int gr = rb + arow + u * 32;
            float4 t4 = (gr < M) ? *(const float4*)&A[gr * K + ac]
                                 : make_float4(0.f, 0.f, 0.f, 0.f);
            ar[u][0] = t4.x; ar[u][1] = t4.y; ar[u][2] = t4.z; ar[u][3] = t4.w;
            br[u] = ldB4(B, bk + u * 16, cb + bc, N);
        }

        for (int k0 = 0; k0 < K; k0 += BK) {
            __syncthreads();
#pragma unroll
            for (int u = 0; u < 2; u++) {
                int row = arow + u * 32;
#pragma unroll
                for (int j = 0; j < 4; j++)
                    As[(ac + j) * 68 + row] = ar[u][j];
                *(float4*)&Bs[(bk + u * 16) * 64 + bc] = br[u];
            }
            __syncthreads();
            if (k0 + BK < K) {
                int kn = k0 + BK;
#pragma unroll
                for (int u = 0; u < 2; u++) {
                    int gr = rb + arow + u * 32;
                    float4 t4 = (gr < M) ? *(const float4*)&A[gr * K + kn + ac]
                                         : make_float4(0.f, 0.f, 0.f, 0.f);
                    ar[u][0] = t4.x; ar[u][1] = t4.y; ar[u][2] = t4.z; ar[u][3] = t4.w;
                    br[u] = ldB4(B, kn + bk + u * 16, cb + bc, N);
                }
            }
#pragma unroll 8
            for (int k = 0; k < BK; k++) {
                float4 a4 = *(const float4*)&As[k * 68 + ty * 4];
                ulonglong2 bp = *(const ulonglong2*)&Bs[k * 64 + tx * 4];
                float av[4] = {a4.x, a4.y, a4.z, a4.w};
#pragma unroll
                for (int i = 0; i < 4; i++) {
                    unsigned r0 = __float_as_uint(av[i]);
                    unsigned long long ad;
                    asm("mov.b64 %0, {%1, %2};" : "=l"(ad) : "r"(r0), "r"(r0));
                    asm("fma.rn.f32x2 %0, %1, %2, %3;"
                        : "=l"(accp[i][0]) : "l"(ad), "l"(bp.x), "l"(accp[i][0]));
                    asm("fma.rn.f32x2 %0, %1, %2, %3;"
                        : "=l"(accp[i][1]) : "l"(ad), "l"(bp.y), "l"(accp[i][1]));
                }
            }
        }
        float acc[4][4];
#pragma unroll
        for (int i = 0; i < 4; i++) {
            acc[i][0] = __uint_as_float((unsigned)accp[i][0]);
            acc[i][1] = __uint_as_float((unsigned)(accp[i][0] >> 32));
            acc[i][2] = __uint_as_float((unsigned)accp[i][1]);
            acc[i][3] = __uint_as_float((unsigned)(accp[i][1] >> 32));
        }
#pragma unroll
        for (int i = 0; i < 4; i++) {
            int r = rb + ty * 4 + i;
            if (r >= M) continue;
#pragma unroll
            for (int j = 0; j < 4; j++) {
                int c = cb + tx * 4 + j;
                if (c >= N) continue;
                float v = acc[i][j];
                if (bias) v += bias[c];
                if (act) v = fmaxf(v, 0.f);
                C[r * N + c] = v;
            }
        }
    }
}

// ---------------- the one kernel ----------------
__global__ void __launch_bounds__(NT, 3)
mega(const float* __restrict__ x, const float* __restrict__ eattr,
     const float* __restrict__ cheb_w, const float* __restrict__ cheb_b,
     const float* __restrict__ eew, const float* __restrict__ eeb,
     const float* __restrict__ w1, const float* __restrict__ b1,
     const float* __restrict__ w2, const float* __restrict__ b2,
     const float* __restrict__ root_w, const float* __restrict__ conv_b,
     const float* __restrict__ ln_g, const float* __restrict__ ln_b,
     const float* __restrict__ aiw, const float* __restrict__ aib,
     const float* __restrict__ aow, const float* __restrict__ aob,
     const float* __restrict__ fw1, const float* __restrict__ fb1,
     const float* __restrict__ fw2, const float* __restrict__ fb2,
     const float* __restrict__ l1g, const float* __restrict__ l1b,
     const float* __restrict__ l2g, const float* __restrict__ l2b,
     const float* __restrict__ lw, const float* __restrict__ lb,
     const int* __restrict__ seq, const int* __restrict__ ei,
     float* __restrict__ out) {
    __shared__ float SB[4352];
    __shared__ float s_a[2][4], s_b[2][4], s_m[2], s_v[2];
    __shared__ float s_r1[4][2], s_r2[4][2];

    const int tid = threadIdx.x;
    const int g = blockIdx.x * NT + tid;
    const int* ss = seq;
    const int* sd = seq + NSEQ;
    const int* esrc = ei;
    const int* edst = ei + NEDGE;

    // ---- P0
    for (int n = g; n < NNODE; n += NTH) { g_degi[n] = 0; g_cnti[n] = 0; }
    for (int it = g; it < NLAY * 320; it += NTH) {
        int l = it / 320, r = it - l * 320;
        int j = r >> 5, tc = r & 31;
        float acc = (j == 9) ? b1[l * 32 + tc] : 0.f;
        for (int u = 0; u < 32; u++) {
            float a = (j < 9) ? eew[j * 32 + u] : eeb[u];
            acc += a * w1[(l * 32 + u) * 32 + tc];
        }
        g_Bm[it] = acc;
    }
    for (int idx = g; idx < NLAY * 16384; idx += NTH) {
        int l = idx >> 14, io = idx & 16383;
        int i = io >> 7, o = io & 127;
        g_Wc[(size_t)l * NHF * WCN + i * WCN + 1280 + o] = root_w[idx];
    }
    gbar();

    // ---- P1
    for (int e = g; e < NSEQ; e += NTH) atomicAdd(&g_degi[ss[e]], 1);
    for (int e = g; e < NEDGE; e += NTH) atomicAdd(&g_cnti[edst[e]], 1);
    for (int it = g; it < NLAY * 16384; it += NTH) {
        int l = it >> 14, io = it & 16383;
        float acc[10];
#pragma unroll
        for (int j = 0; j < 10; j++) acc[j] = 0.f;
        const float* wp = w2 + (size_t)l * 32 * 16384 + io;
        const float* bp = g_Bm + l * 320;
#pragma unroll 8
        for (int tc = 0; tc < 32; tc++) {
            float v = wp[(size_t)tc * 16384];
#pragma unroll
            for (int j = 0; j < 10; j++) acc[j] += bp[j * 32 + tc] * v;
        }
        acc[9] += b2[(size_t)l * 16384 + io];
        int i = io >> 7, o = io & 127;
        float* dst = g_Wc + (size_t)l * NHF * WCN + i * WCN + o;
#pragma unroll
        for (int j = 0; j < 10; j++) dst[j * 128] = acc[j];
    }
    gbar();

    // ---- P2
    for (int n = g; n < NNODE; n += NTH) {
        int c = g_degi[n];
        g_dinv[n] = (c > 0) ? rsqrtf((float)c) : 0.f;
    }
    if (blockIdx.x == 0) {
        int* part = (int*)SB;
        int base = tid * 4;
        int v0[4]; int sloc = 0;
#pragma unroll
        for (int j = 0; j < 4; j++) {
            int idx = base + j;
            v0[j] = (idx < NNODE) ? g_cnti[idx] : 0;
            sloc += v0[j];
        }
        part[tid] = sloc;
        __syncthreads();
        for (int off = 1; off < 256; off <<= 1) {
            int xv = (tid >= off) ? part[tid - off] : 0;
            __syncthreads();
            part[tid] += xv;
            __syncthreads();
        }
        int run = (tid == 0) ? 0 : part[tid - 1];
#pragma unroll
        for (int j = 0; j < 4; j++) {
            int idx = base + j;
            run += v0[j];
            if (idx < NNODE) g_rp[idx + 1] = run;
        }
        if (tid == 0) g_rp[0] = 0;
    }
    gbar();

    // ---- P3: lap1 + CSR fill
    for (int it = g; it < NNODE * NNF_; it += NTH) {
        int n = it / NNF_, f = it - n * NNF_;
        float dn = g_dinv[n];
        float acc = 0.f;
        for (int e = 0; e < NSEQ; e++) {
            if (sd[e] == n) {
                int s = ss[e];
                acc += -(g_dinv[s] * dn) * x[s * NNF_ + f];
            }
        }
        g_tx1[it] = acc;
    }
    {
        int gr = NTH - 1 - g;
        if (gr < NNODE && gr >= 0) {
            int p = g_rp[gr];
            for (int e = 0; e < NEDGE; e++)
                if (edst[e] == gr) g_eid[p++] = e;
        }
    }
    gbar();

    // ---- P4: lap2
    for (int it = g; it < NNODE * NNF_; it += NTH) {
        int n = it / NNF_, f = it - n * NNF_;
        float dn = g_dinv[n];
        float acc = 0.f;
        for (int e = 0; e < NSEQ; e++) {
            if (sd[e] == n) {
                int s = ss[e];
                acc += -(g_dinv[s] * dn) * g_tx1[s * NNF_ + f];
            }
        }
        g_tx2[it] = 2.f * acc - x[it];
    }
    gbar();

    // ---- P5: ChebConv
    for (int it = g; it < NNODE * NHF; it += NTH) {
        int n = it >> 7, o = it & 127;
        const float* xr = x + n * NNF_;
        const float* t1 = g_tx1 + n * NNF_;
        const float* t2 = g_tx2 + n * NNF_;
        float acc = cheb_b[o];
#pragma unroll
        for (int f = 0; f < NNF_; f++) {
            acc += xr[f] * cheb_w[f * NHF + o];
            acc += t1[f] * cheb_w[2176 + f * NHF + o];
            acc += t2[f] * cheb_w[4352 + f * NHF + o];
        }
        g_hin[it] = acc;
    }
    gbar();

    // ---- conv layers ----
    for (int l = 0; l < NLAY; l++) {
        gemm_tiles(g_hin, g_Wc + (size_t)l * NHF * WCN, nullptr, g_P,
                   NNODE, WCN, NHF, 0, SB);
        gbar();
        {
            int half = tid >> 7, o = tid & 127;
            int w = (tid >> 5) & 3, lane = tid & 31;
            for (int ii = blockIdx.x; ii < NNODE / 2; ii += NB) {
                int n = ii * 2 + half;
                float acc = g_P[n * WCN + 1280 + o] + conv_b[l * 128 + o];
                int e0 = g_rp[n], e1 = g_rp[n + 1];
                for (int idx = e0; idx < e1; idx++) {
                    int e = g_eid[idx];
                    int s = esrc[e];
                    const float* zp = eattr + e * 9;
                    const float* Ps = g_P + s * WCN + o;
                    float m = Ps[1152];
#pragma unroll
                    for (int j = 0; j < 9; j++) m += zp[j] * Ps[j * 128];
                    acc += m;
                }
                float nh = acc + ((l > 0) ? g_h[n * 128 + o] : 0.f);
                g_h[n * 128 + o] = nh;
                float a = nh, b = nh * nh;
#pragma unroll
                for (int off = 16; off; off >>= 1) {
                    a += __shfl_down_sync(0xffffffffu, a, off);
                    b += __shfl_down_sync(0xffffffffu, b, off);
                }
                if (lane == 0) { s_a[half][w] = a; s_b[half][w] = b; }
                __syncthreads();
                if (o == 0) {
                    float ta = s_a[half][0] + s_a[half][1] + s_a[half][2] + s_a[half][3];
                    float tb = s_b[half][0] + s_b[half][1] + s_b[half][2] + s_b[half][3];
                    s_m[half] = ta * (1.f / 128.f);
                    s_v[half] = tb * (1.f / 128.f);
                }
                __syncthreads();
                float mean = s_m[half];
                float var = s_v[half] - mean * mean;
                int ni = (l + 1) % NLAY;
                float z = (nh - mean) * rsqrtf(var + EPSF) * ln_g[ni * 128 + o] + ln_b[ni * 128 + o];
                float act = geluf(z);
                if (l < NLAY - 1) {
                    g_hin[n * 128 + o] = act;
                } else {
                    g_t[n * DM + o] = act;
                    if (o < 32) {
                        int p = n % SEQL;
                        int i2 = o >> 1;
                        float div = expf((float)(2 * i2) * (-0.28782313662425576f));
                        float ang = (float)p * div;
                        g_t[n * DM + 128 + o] = (o & 1) ? cosf(ang) : sinf(ang);
                    }
                }
            }
        }
        gbar();
    }

    // ---- transformer: qkv layer 0 ----
    gemm_tiles(g_t, aiw, aib, g_qkv, NNODE, 480, DM, 0, SB);
    gbar();

    for (int tl = 0; tl < 3; tl++) {
        // ---- attention: 128 units (b, h, half), online softmax, f4 staging ----
        {
            float* Ks = SB;
            float* Vs = SB + SEQL * 20;
            const float4* qkv4 = (const float4*)g_qkv;
            for (int u = blockIdx.x; u < 128; u += NB) {
                int b = u >> 4, rem = u & 15;
                int h = rem >> 1, half = rem & 1;
                for (int i = tid; i < SEQL * 5; i += NT) {
                    int r = i / 5, d4 = i - r * 5;
                    int base = (b * SEQL + r) * 120 + h * 5 + d4;
                    ((float4*)Ks)[i] = qkv4[base + 40];
                    ((float4*)Vs)[i] = qkv4[base + 80];
                }
                __syncthreads();
                int cnt = half ? 53 : 54;
                if (tid < cnt) {
                    int n = b * SEQL + half * 54 + tid;
                    float q[20];
#pragma unroll
                    for (int d4 = 0; d4 < 5; d4++) {
                        float4 t4 = qkv4[n * 120 + h * 5 + d4];
                        q[d4*4+0] = t4.x * 0.22360679774997896f;
                        q[d4*4+1] = t4.y * 0.22360679774997896f;
                        q[d4*4+2] = t4.z * 0.22360679774997896f;
                        q[d4*4+3] = t4.w * 0.22360679774997896f;
                    }
                    float m = -1e30f, lsum = 0.f, acc[20];
#pragma unroll
                    for (int d = 0; d < 20; d++) acc[d] = 0.f;
                    for (int k = 0; k < SEQL; k++) {
                        float s = 0.f;
#pragma unroll
                        for (int d = 0; d < 20; d++) s += q[d] * Ks[k * 20 + d];
                        float mn = fmaxf(m, s);
                        float corr = __expf(m - mn);
                        float p = __expf(s - mn);
                        lsum = lsum * corr + p;
#pragma unroll
                        for (int d = 0; d < 20; d++) acc[d] = acc[d] * corr + p * Vs[k * 20 + d];
                        m = mn;
                    }
                    float inv = 1.f / lsum;
#pragma unroll
                    for (int d = 0; d < 20; d++)
                        g_att[n * DM + h * 20 + d] = acc[d] * inv;
                }
                __syncthreads();
            }
        }
        gbar();

        // ---- X phase: 4 rows/block, 2 warps/row, float4 weight loads ----
        {
            float* sA = SB;              // [4][160] attention rows
            float* sT = SB + 640;        // [4][160]
            float* sF = SB + 1664;       // [4][256]
            const float* Wo  = aow + (size_t)tl * 25600;
            const float* bo  = aob + tl * 160;
            const float* W1  = fw1 + (size_t)tl * 40960;
            const float* bb1 = fb1 + tl * 256;
            const float* W2  = fw2 + (size_t)tl * 40960;
            const float* bb2 = fb2 + tl * 160;
            const float* g1  = l1g + tl * 160;
            const float* be1 = l1b + tl * 160;
            const float* g2v = l2g + tl * 160;
            const float* be2 = l2b + tl * 160;
            const int w = tid >> 5, lane = tid & 31;
            const int rowi = w >> 1, side = w & 1;
            const int gg = side * 20 + lane;      // 40-group steps
            const bool act20 = lane < 20;
            const int gf = side * 32 + lane;      // 64-group step (FF1)

            for (int rt = blockIdx.x; rt < NNODE / 4; rt += NB) {
                int r0 = rt * 4;
                for (int i = tid; i < 4 * DM; i += NT) {
                    int rr = i / DM, c = i - rr * DM;
                    sT[i] = g_t[(r0 + rr) * DM + c];
                    sA[i] = g_att[(r0 + rr) * DM + c];
                }
                __syncthreads();
                int r = r0 + rowi;

                // step 1: out-proj + residual + LN1
                float4 a4 = make_float4(0.f, 0.f, 0.f, 0.f);
                if (act20) {
                    for (int k = 0; k < DM; k++) {
                        float av = sA[rowi * DM + k];
                        float4 w4 = ((const float4*)(Wo + k * 160))[gg];
                        a4.x += av * w4.x; a4.y += av * w4.y;
                        a4.z += av * w4.z; a4.w += av * w4.w;
                    }
                }
                float4 v4 = make_float4(0.f, 0.f, 0.f, 0.f);
                float s1 = 0.f, s2 = 0.f;
                if (act20) {
                    float4 t4 = ((const float4*)(sT + rowi * DM))[gg];
                    float4 b4 = ((const float4*)bo)[gg];
                    v4.x = t4.x + a4.x + b4.x; v4.y = t4.y + a4.y + b4.y;
                    v4.z = t4.z + a4.z + b4.z; v4.w = t4.w + a4.w + b4.w;
                    s1 = v4.x + v4.y + v4.z + v4.w;
                    s2 = v4.x*v4.x + v4.y*v4.y + v4.z*v4.z + v4.w*v4.w;
                }
#pragma unroll
                for (int off = 16; off; off >>= 1) {
                    s1 += __shfl_xor_sync(0xffffffffu, s1, off);
                    s2 += __shfl_xor_sync(0xffffffffu, s2, off);
                }
                if (lane == 0) { s_r1[rowi][side] = s1; s_r2[rowi][side] = s2; }
                __syncthreads();
                {
                    float mean = (s_r1[rowi][0] + s_r1[rowi][1]) * (1.f / 160.f);
                    float var  = (s_r2[rowi][0] + s_r2[rowi][1]) * (1.f / 160.f) - mean * mean;
                    float rstd = rsqrtf(var + EPSF);
                    if (act20) {
                        float4 g4 = ((const float4*)g1)[gg];
                        float4 e4 = ((const float4*)be1)[gg];
                        float4 n4;
                        n4.x = (v4.x - mean) * rstd * g4.x + e4.x;
                        n4.y = (v4.y - mean) * rstd * g4.y + e4.y;
                        n4.z = (v4.z - mean) * rstd * g4.z + e4.z;
                        n4.w = (v4.w - mean) * rstd * g4.w + e4.w;
                        ((float4*)(sT + rowi * DM))[gg] = n4;
                    }
                }
                __syncthreads();

                // step 2: FF1 + relu
                {
                    float4 f4 = make_float4(0.f, 0.f, 0.f, 0.f);
                    for (int k = 0; k < DM; k++) {
                        float a = sT[rowi * DM + k];
                        float4 w4 = ((const float4*)(W1 + k * 256))[gf];
                        f4.x += a * w4.x; f4.y += a * w4.y;
                        f4.z += a * w4.z; f4.w += a * w4.w;
                    }
                    float4 b4 = ((const float4*)bb1)[gf];
                    f4.x = fmaxf(f4.x + b4.x, 0.f); f4.y = fmaxf(f4.y + b4.y, 0.f);
                    f4.z = fmaxf(f4.z + b4.z, 0.f); f4.w = fmaxf(f4.w + b4.w, 0.f);
                    ((float4*)(sF + rowi * 256))[gf] = f4;
                }
                __syncthreads();

                // step 3: FF2 + residual + LN2
                a4 = make_float4(0.f, 0.f, 0.f, 0.f);
                if (act20) {
                    for (int k = 0; k < 256; k++) {
                        float a = sF[rowi * 256 + k];
                        float4 w4 = ((const float4*)(W2 + k * 160))[gg];
                        a4.x += a * w4.x; a4.y += a * w4.y;
                        a4.z += a * w4.z; a4.w += a * w4.w;
                    }
                }
                s1 = 0.f; s2 = 0.f;
                if (act20) {
                    float4 t4 = ((const float4*)(sT + rowi * DM))[gg];
                    float4 b4 = ((const float4*)bb2)[gg];
                    v4.x = t4.x + a4.x + b4.x; v4.y = t4.y + a4.y + b4.y;
                    v4.z = t4.z + a4.z + b4.z; v4.w = t4.w + a4.w + b4.w;
                    s1 = v4.x + v4.y + v4.z + v4.w;
                    s2 = v4.x*v4.x + v4.y*v4.y + v4.z*v4.z + v4.w*v4.w;
                }
#pragma unroll
                for (int off = 16; off; off >>= 1) {
                    s1 += __shfl_xor_sync(0xffffffffu, s1, off);
                    s2 += __shfl_xor_sync(0xffffffffu, s2, off);
                }
                if (lane == 0) { s_r1[rowi][side] = s1; s_r2[rowi][side] = s2; }
                __syncthreads();
                {
                    float mean = (s_r1[rowi][0] + s_r1[rowi][1]) * (1.f / 160.f);
                    float var  = (s_r2[rowi][0] + s_r2[rowi][1]) * (1.f / 160.f) - mean * mean;
                    float rstd = rsqrtf(var + EPSF);
                    if (act20) {
                        float4 g4 = ((const float4*)g2v)[gg];
                        float4 e4 = ((const float4*)be2)[gg];
                        float4 n4;
                        n4.x = (v4.x - mean) * rstd * g4.x + e4.x;
                        n4.y = (v4.y - mean) * rstd * g4.y + e4.y;
                        n4.z = (v4.z - mean) * rstd * g4.z + e4.z;
                        n4.w = (v4.w - mean) * rstd * g4.w + e4.w;
                        ((float4*)(sT + rowi * DM))[gg] = n4;
                        ((float4*)(g_t + r * DM))[gg] = n4;
                    }
                }
                __syncthreads();

                // step 4: next-layer qkv / final head
                if (tl < 2) {
                    const float* Wq = aiw + (size_t)(tl + 1) * 76800;
                    const float* bq = aib + (tl + 1) * 480;
                    int ga = side * 60 + lane;
                    int gb = side * 60 + 32 + lane;
                    bool actb = lane < 28;
                    float4 q0 = make_float4(0.f, 0.f, 0.f, 0.f);
                    float4 q1 = make_float4(0.f, 0.f, 0.f, 0.f);
                    for (int k = 0; k < DM; k++) {
                        float a = sT[rowi * DM + k];
                        const float4* Wr = (const float4*)(Wq + k * 480);
                        float4 wa = Wr[ga];
                        q0.x += a * wa.x; q0.y += a * wa.y;
                        q0.z += a * wa.z; q0.w += a * wa.w;
                        if (actb) {
                            float4 wb = Wr[gb];
                            q1.x += a * wb.x; q1.y += a * wb.y;
                            q1.z += a * wb.z; q1.w += a * wb.w;
                        }
                    }
                    {
                        float4 ba = ((const float4*)bq)[ga];
                        q0.x += ba.x; q0.y += ba.y; q0.z += ba.z; q0.w += ba.w;
                        ((float4*)(g_qkv + r * 480))[ga] = q0;
                        if (actb) {
                            float4 bb = ((const float4*)bq)[gb];
                            q1.x += bb.x; q1.y += bb.y; q1.z += bb.z; q1.w += bb.w;
                            ((float4*)(g_qkv + r * 480))[gb] = q1;
                        }
                    }
                } else {
                    if (side == 0 && lane < 3) {
                        float a = lb[lane];
                        for (int k = 0; k < DM; k++)
                            a += sT[rowi * DM + k] * lw[k * 3 + lane];
                        out[r * 3 + lane] = a;
                    }
                }
                __syncthreads();
            }
        }
        if (tl < 2) gbar();
    }
}

// ---------------- host ----------------
extern "C" void kernel_launch(void* const* d_in, const int* in_sizes, int n_in,
                              void* d_out, int out_size) {
    mega<<<NB, NT>>>(
        (const float*)d_in[0],  (const float*)d_in[1],  (const float*)d_in[2],
        (const float*)d_in[3],  (const float*)d_in[4],  (const float*)d_in[5],
        (const float*)d_in[6],  (const float*)d_in[7],  (const float*)d_in[8],
        (const float*)d_in[9],  (const float*)d_in[10], (const float*)d_in[11],
        (const float*)d_in[12], (const float*)d_in[13], (const float*)d_in[14],
        (const float*)d_in[15], (const float*)d_in[16], (const float*)d_in[17],
        (const float*)d_in[18], (const float*)d_in[19], (const float*)d_in[20],
        (const float*)d_in[21], (const float*)d_in[22], (const float*)d_in[23],
        (const float*)d_in[24], (const float*)d_in[25], (const float*)d_in[26],
        (const float*)d_in[27], (const int*)d_in[28],   (const int*)d_in[29],
        (float*)d_out);
}

// round 9
// speedup vs baseline: 1.4235x; 1.4235x over previous
#include <cuda_runtime.h>
#include <math.h>

#define NNODE 856
#define NEDGE 2896
#define NSEQ  1696
#define NHF   128
#define NNF_  17
#define DM    160
#define SEQL  107
#define NLAY  10
#define WCN   1408
#define EPSF  1e-5f
#define NB    444
#define NT    256
#define NTH   (NB*NT)
#define BK    32

// ---------------- device scratch ----------------
__device__ float g_dinv[NNODE];
__device__ int   g_degi[NNODE];
__device__ float g_tx1[NNODE * NNF_];
__device__ float g_tx2[NNODE * NNF_];
__device__ float g_h[NNODE * NHF];
__device__ float g_hin[NNODE * NHF];
__device__ float g_Bm[NLAY * 320];
__device__ float g_Wc[NLAY * NHF * WCN];
__device__ float g_P[NNODE * WCN];
__device__ int   g_cnti[NNODE];
__device__ int   g_rp[NNODE + 1];
__device__ int   g_eid[NEDGE];
__device__ float g_t[NNODE * DM];
__device__ float g_qkv[NNODE * 480];
__device__ float g_att[NNODE * DM];
__device__ unsigned g_barcnt;
__device__ volatile unsigned g_bargen;

// ---------------- grid barrier (R5 heavy version — known-good) ----------------
__device__ __forceinline__ void gbar() {
    __syncthreads();
    __threadfence();                       // publish my writes to L2
    if (threadIdx.x == 0) {
        unsigned gen = g_bargen;
        if (atomicAdd(&g_barcnt, 1u) == NB - 1u) {
            g_barcnt = 0u;
            __threadfence();
            g_bargen = gen + 1u;
        } else {
            while (g_bargen == gen) __nanosleep(32);
        }
    }
    __syncthreads();
    __threadfence();                       // acquire: invalidate stale L1
}

__device__ __forceinline__ float geluf(float x) {
    return 0.5f * x * (1.0f + erff(x * 0.70710678118654752f));
}

// guarded float4 B-tile load: row always valid, col may exceed N
__device__ __forceinline__ float4 ldB4(const float* __restrict__ B, int row,
                                       int col, int N) {
    if (col + 3 < N) return *(const float4*)&B[row * N + col];
    float4 r = make_float4(0.f, 0.f, 0.f, 0.f);
    if (col     < N) r.x = B[row * N + col];
    if (col + 1 < N) r.y = B[row * N + col + 1];
    if (col + 2 < N) r.z = B[row * N + col + 2];
    return r;
}

// ---------------- tiled GEMM phase: C = act(A@B + bias) ----------------
// 64x64 tile, BK=32, register-staged pipeline, packed f32x2 FMA. K % 32 == 0.
__device__ void gemm_tiles(const float* __restrict__ A, const float* __restrict__ B,
                           const float* __restrict__ bias, float* __restrict__ C,
                           int M, int N, int K, int act, float* SB) {
    float* As = SB;              // [BK][68] padded
    float* Bs = SB + BK * 68;    // [BK][64]
    const int ntc = (N + 63) >> 6;
    const int ntiles = ((M + 63) >> 6) * ntc;
    const int tid = threadIdx.x;
    const int tx = tid & 15, ty = tid >> 4;
    const int arow = tid >> 3;
    const int ac   = (tid & 7) * 4;
    const int bk   = tid >> 4;
    const int bc   = (tid & 15) * 4;

    for (int t = blockIdx.x; t < ntiles; t += NB) {
        int tr = t / ntc;
        int rb = tr * 64, cb = (t - tr * ntc) * 64;
        unsigned long long accp[4][2];
#pragma unroll
        for (int i = 0; i < 4; i++) { accp[i][0] = 0ull; accp[i][1] = 0ull; }

        float ar[2][4];
        float4 br[2];
#pragma unroll
        for (int u = 0; u < 2; u++) {
            int gr = rb + arow + u * 32;
            float4 t4 = (gr < M) ? *(const float4*)&A[gr * K + ac]
                                 : make_float4(0.f, 0.f, 0.f, 0.f);
            ar[u][0] = t4.x; ar[u][1] = t4.y; ar[u][2] = t4.z; ar[u][3] = t4.w;
            br[u] = ldB4(B, bk + u * 16, cb + bc, N);
        }

        for (int k0 = 0; k0 < K; k0 += BK) {
            __syncthreads();
#pragma unroll
            for (int u = 0; u < 2; u++) {
                int row = arow + u * 32;
#pragma unroll
                for (int j = 0; j < 4; j++)
                    As[(ac + j) * 68 + row] = ar[u][j];
                *(float4*)&Bs[(bk + u * 16) * 64 + bc] = br[u];
            }
            __syncthreads();
            if (k0 + BK < K) {
                int kn = k0 + BK;
#pragma unroll
                for (int u = 0; u < 2; u++) {
                    int gr = rb + arow + u * 32;
                    float4 t4 = (gr < M) ? *(const float4*)&A[gr * K + kn + ac]
                                         : make_float4(0.f, 0.f, 0.f, 0.f);
                    ar[u][0] = t4.x; ar[u][1] = t4.y; ar[u][2] = t4.z; ar[u][3] = t4.w;
                    br[u] = ldB4(B, kn + bk + u * 16, cb + bc, N);
                }
            }
#pragma unroll 8
            for (int k = 0; k < BK; k++) {
                float4 a4 = *(const float4*)&As[k * 68 + ty * 4];
                ulonglong2 bp = *(const ulonglong2*)&Bs[k * 64 + tx * 4];
                float av[4] = {a4.x, a4.y, a4.z, a4.w};
#pragma unroll
                for (int i = 0; i < 4; i++) {
                    unsigned r0 = __float_as_uint(av[i]);
                    unsigned long long ad;
                    asm("mov.b64 %0, {%1, %2};" : "=l"(ad) : "r"(r0), "r"(r0));
                    asm("fma.rn.f32x2 %0, %1, %2, %3;"
                        : "=l"(accp[i][0]) : "l"(ad), "l"(bp.x), "l"(accp[i][0]));
                    asm("fma.rn.f32x2 %0, %1, %2, %3;"
                        : "=l"(accp[i][1]) : "l"(ad), "l"(bp.y), "l"(accp[i][1]));
                }
            }
        }
        float acc[4][4];
#pragma unroll
        for (int i = 0; i < 4; i++) {
            acc[i][0] = __uint_as_float((unsigned)accp[i][0]);
            acc[i][1] = __uint_as_float((unsigned)(accp[i][0] >> 32));
            acc[i][2] = __uint_as_float((unsigned)accp[i][1]);
            acc[i][3] = __uint_as_float((unsigned)(accp[i][1] >> 32));
        }
#pragma unroll
        for (int i = 0; i < 4; i++) {
            int r = rb + ty * 4 + i;
            if (r >= M) continue;
#pragma unroll
            for (int j = 0; j < 4; j++) {
                int c = cb + tx * 4 + j;
                if (c >= N) continue;
                float v = acc[i][j];
                if (bias) v += bias[c];
                if (act) v = fmaxf(v, 0.f);
                C[r * N + c] = v;
            }
        }
    }
}

// ---------------- the one kernel ----------------
__global__ void __launch_bounds__(NT, 3)
mega(const float* __restrict__ x, const float* __restrict__ eattr,
     const float* __restrict__ cheb_w, const float* __restrict__ cheb_b,
     const float* __restrict__ eew, const float* __restrict__ eeb,
     const float* __restrict__ w1, const float* __restrict__ b1,
     const float* __restrict__ w2, const float* __restrict__ b2,
     const float* __restrict__ root_w, const float* __restrict__ conv_b,
     const float* __restrict__ ln_g, const float* __restrict__ ln_b,
     const float* __restrict__ aiw, const float* __restrict__ aib,
     const float* __restrict__ aow, const float* __restrict__ aob,
     const float* __restrict__ fw1, const float* __restrict__ fb1,
     const float* __restrict__ fw2, const float* __restrict__ fb2,
     const float* __restrict__ l1g, const float* __restrict__ l1b,
     const float* __restrict__ l2g, const float* __restrict__ l2b,
     const float* __restrict__ lw, const float* __restrict__ lb,
     const int* __restrict__ seq, const int* __restrict__ ei,
     float* __restrict__ out) {
    __shared__ float SB[4352];
    __shared__ float s_a[2][4], s_b[2][4], s_m[2], s_v[2];

    const int tid = threadIdx.x;
    const int g = blockIdx.x * NT + tid;
    const int* ss = seq;
    const int* sd = seq + NSEQ;
    const int* esrc = ei;
    const int* edst = ei + NEDGE;

    // ---- P0
    for (int n = g; n < NNODE; n += NTH) { g_degi[n] = 0; g_cnti[n] = 0; }
    for (int it = g; it < NLAY * 320; it += NTH) {
        int l = it / 320, r = it - l * 320;
        int j = r >> 5, tc = r & 31;
        float acc = (j == 9) ? b1[l * 32 + tc] : 0.f;
        for (int u = 0; u < 32; u++) {
            float a = (j < 9) ? eew[j * 32 + u] : eeb[u];
            acc += a * w1[(l * 32 + u) * 32 + tc];
        }
        g_Bm[it] = acc;
    }
    for (int idx = g; idx < NLAY * 16384; idx += NTH) {
        int l = idx >> 14, io = idx & 16383;
        int i = io >> 7, o = io & 127;
        g_Wc[(size_t)l * NHF * WCN + i * WCN + 1280 + o] = root_w[idx];
    }
    gbar();

    // ---- P1
    for (int e = g; e < NSEQ; e += NTH) atomicAdd(&g_degi[ss[e]], 1);
    for (int e = g; e < NEDGE; e += NTH) atomicAdd(&g_cnti[edst[e]], 1);
    for (int it = g; it < NLAY * 16384; it += NTH) {
        int l = it >> 14, io = it & 16383;
        float acc[10];
#pragma unroll
        for (int j = 0; j < 10; j++) acc[j] = 0.f;
        const float* wp = w2 + (size_t)l * 32 * 16384 + io;
        const float* bp = g_Bm + l * 320;
#pragma unroll 8
        for (int tc = 0; tc < 32; tc++) {
            float v = wp[(size_t)tc * 16384];
#pragma unroll
            for (int j = 0; j < 10; j++) acc[j] += bp[j * 32 + tc] * v;
        }
        acc[9] += b2[(size_t)l * 16384 + io];
        int i = io >> 7, o = io & 127;
        float* dst = g_Wc + (size_t)l * NHF * WCN + i * WCN + o;
#pragma unroll
        for (int j = 0; j < 10; j++) dst[j * 128] = acc[j];
    }
    gbar();

    // ---- P2
    for (int n = g; n < NNODE; n += NTH) {
        int c = g_degi[n];
        g_dinv[n] = (c > 0) ? rsqrtf((float)c) : 0.f;
    }
    if (blockIdx.x == 0) {
        int* part = (int*)SB;
        int base = tid * 4;
        int v0[4]; int sloc = 0;
#pragma unroll
        for (int j = 0; j < 4; j++) {
            int idx = base + j;
            v0[j] = (idx < NNODE) ? g_cnti[idx] : 0;
            sloc += v0[j];
        }
        part[tid] = sloc;
        __syncthreads();
        for (int off = 1; off < 256; off <<= 1) {
            int xv = (tid >= off) ? part[tid - off] : 0;
            __syncthreads();
            part[tid] += xv;
            __syncthreads();
        }
        int run = (tid == 0) ? 0 : part[tid - 1];
#pragma unroll
        for (int j = 0; j < 4; j++) {
            int idx = base + j;
            run += v0[j];
            if (idx < NNODE) g_rp[idx + 1] = run;
        }
        if (tid == 0) g_rp[0] = 0;
    }
    gbar();

    // ---- P3: lap1 + CSR fill
    for (int it = g; it < NNODE * NNF_; it += NTH) {
        int n = it / NNF_, f = it - n * NNF_;
        float dn = g_dinv[n];
        float acc = 0.f;
        for (int e = 0; e < NSEQ; e++) {
            if (sd[e] == n) {
                int s = ss[e];
                acc += -(g_dinv[s] * dn) * x[s * NNF_ + f];
            }
        }
        g_tx1[it] = acc;
    }
    {
        int gr = NTH - 1 - g;
        if (gr < NNODE && gr >= 0) {
            int p = g_rp[gr];
            for (int e = 0; e < NEDGE; e++)
                if (edst[e] == gr) g_eid[p++] = e;
        }
    }
    gbar();

    // ---- P4: lap2
    for (int it = g; it < NNODE * NNF_; it += NTH) {
        int n = it / NNF_, f = it - n * NNF_;
        float dn = g_dinv[n];
        float acc = 0.f;
        for (int e = 0; e < NSEQ; e++) {
            if (sd[e] == n) {
                int s = ss[e];
                acc += -(g_dinv[s] * dn) * g_tx1[s * NNF_ + f];
            }
        }
        g_tx2[it] = 2.f * acc - x[it];
    }
    gbar();

    // ---- P5: ChebConv
    for (int it = g; it < NNODE * NHF; it += NTH) {
        int n = it >> 7, o = it & 127;
        const float* xr = x + n * NNF_;
        const float* t1 = g_tx1 + n * NNF_;
        const float* t2 = g_tx2 + n * NNF_;
        float acc = cheb_b[o];
#pragma unroll
        for (int f = 0; f < NNF_; f++) {
            acc += xr[f] * cheb_w[f * NHF + o];
            acc += t1[f] * cheb_w[2176 + f * NHF + o];
            acc += t2[f] * cheb_w[4352 + f * NHF + o];
        }
        g_hin[it] = acc;
    }
    gbar();

    // ---- conv layers ----
    for (int l = 0; l < NLAY; l++) {
        gemm_tiles(g_hin, g_Wc + (size_t)l * NHF * WCN, nullptr, g_P,
                   NNODE, WCN, NHF, 0, SB);
        gbar();
        {
            int half = tid >> 7, o = tid & 127;
            int w = (tid >> 5) & 3, lane = tid & 31;
            for (int ii = blockIdx.x; ii < NNODE / 2; ii += NB) {
                int n = ii * 2 + half;
                float acc = g_P[n * WCN + 1280 + o] + conv_b[l * 128 + o];
                int e0 = g_rp[n], e1 = g_rp[n + 1];
                for (int idx = e0; idx < e1; idx++) {
                    int e = g_eid[idx];
                    int s = esrc[e];
                    const float* zp = eattr + e * 9;
                    const float* Ps = g_P + s * WCN + o;
                    float m = Ps[1152];
#pragma unroll
                    for (int j = 0; j < 9; j++) m += zp[j] * Ps[j * 128];
                    acc += m;
                }
                float nh = acc + ((l > 0) ? g_h[n * 128 + o] : 0.f);
                g_h[n * 128 + o] = nh;
                float a = nh, b = nh * nh;
#pragma unroll
                for (int off = 16; off; off >>= 1) {
                    a += __shfl_down_sync(0xffffffffu, a, off);
                    b += __shfl_down_sync(0xffffffffu, b, off);
                }
                if (lane == 0) { s_a[half][w] = a; s_b[half][w] = b; }
                __syncthreads();
                if (o == 0) {
                    float ta = s_a[half][0] + s_a[half][1] + s_a[half][2] + s_a[half][3];
                    float tb = s_b[half][0] + s_b[half][1] + s_b[half][2] + s_b[half][3];
                    s_m[half] = ta * (1.f / 128.f);
                    s_v[half] = tb * (1.f / 128.f);
                }
                __syncthreads();
                float mean = s_m[half];
                float var = s_v[half] - mean * mean;
                int ni = (l + 1) % NLAY;
                float z = (nh - mean) * rsqrtf(var + EPSF) * ln_g[ni * 128 + o] + ln_b[ni * 128 + o];
                float act = geluf(z);
                if (l < NLAY - 1) {
                    g_hin[n * 128 + o] = act;
                } else {
                    g_t[n * DM + o] = act;
                    if (o < 32) {
                        int p = n % SEQL;
                        int i2 = o >> 1;
                        float div = expf((float)(2 * i2) * (-0.28782313662425576f));
                        float ang = (float)p * div;
                        g_t[n * DM + 128 + o] = (o & 1) ? cosf(ang) : sinf(ang);
                    }
                }
            }
        }
        gbar();
    }

    // ---- transformer: qkv layer 0 ----
    gemm_tiles(g_t, aiw, aib, g_qkv, NNODE, 480, DM, 0, SB);
    gbar();

    for (int tl = 0; tl < 3; tl++) {
        // ---- attention: 128 units (b, h, half), online softmax ----
        {
            float* Ks = SB;
            float* Vs = SB + SEQL * 20;
            for (int u = blockIdx.x; u < 128; u += NB) {
                int b = u >> 4, rem = u & 15;
                int h = rem >> 1, half = rem & 1;
                for (int i = tid; i < SEQL * 20; i += NT) {
                    int r = i / 20, d = i - r * 20;
                    int n = b * SEQL + r;
                    Ks[i] = g_qkv[n * 480 + 160 + h * 20 + d];
                    Vs[i] = g_qkv[n * 480 + 320 + h * 20 + d];
                }
                __syncthreads();
                int cnt = half ? 53 : 54;
                if (tid < cnt) {
                    int n = b * SEQL + half * 54 + tid;
                    float q[20];
#pragma unroll
                    for (int d = 0; d < 20; d++)
                        q[d] = g_qkv[n * 480 + h * 20 + d] * 0.22360679774997896f;
                    float m = -1e30f, lsum = 0.f, acc[20];
#pragma unroll
                    for (int d = 0; d < 20; d++) acc[d] = 0.f;
                    for (int k = 0; k < SEQL; k++) {
                        float s = 0.f;
#pragma unroll
                        for (int d = 0; d < 20; d++) s += q[d] * Ks[k * 20 + d];
                        float mn = fmaxf(m, s);
                        float corr = __expf(m - mn);
                        float p = __expf(s - mn);
                        lsum = lsum * corr + p;
#pragma unroll
                        for (int d = 0; d < 20; d++) acc[d] = acc[d] * corr + p * Vs[k * 20 + d];
                        m = mn;
                    }
                    float inv = 1.f / lsum;
#pragma unroll
                    for (int d = 0; d < 20; d++)
                        g_att[n * DM + h * 20 + d] = acc[d] * inv;
                }
                __syncthreads();
            }
        }
        gbar();

        // ---- X phase (R5 structure): 8 rows/block, 1 warp/row ----
        {
            float* sT = SB;            // [8][160]
            float* sF = SB + 1280;     // [8][256]
            const float* Wo  = aow + (size_t)tl * 25600;
            const float* bo  = aob + tl * 160;
            const float* W1  = fw1 + (size_t)tl * 40960;
            const float* bb1 = fb1 + tl * 256;
            const float* W2  = fw2 + (size_t)tl * 40960;
            const float* bb2 = fb2 + tl * 160;
            const float* g1  = l1g + tl * 160;
            const float* be1 = l1b + tl * 160;
            const float* g2v = l2g + tl * 160;
            const float* be2 = l2b + tl * 160;
            int w = tid >> 5, lane = tid & 31;
            for (int rt = blockIdx.x; rt < SEQL; rt += NB) {
                int r0 = rt * 8;
                for (int i = tid; i < 8 * DM; i += NT) {
                    int r = i / DM, c = i - r * DM;
                    sT[i] = g_t[(r0 + r) * DM + c];
                }
                __syncthreads();
                int r = r0 + w;
                float acc[5], v[5];
#pragma unroll
                for (int j = 0; j < 5; j++) acc[j] = 0.f;
                for (int k = 0; k < DM; k++) {
                    float av = g_att[r * DM + k];
#pragma unroll
                    for (int j = 0; j < 5; j++)
                        acc[j] += av * Wo[k * 160 + lane + 32 * j];
                }
                float s1 = 0.f, s2 = 0.f;
#pragma unroll
                for (int j = 0; j < 5; j++) {
                    int c = lane + 32 * j;
                    v[j] = sT[w * DM + c] + acc[j] + bo[c];
                    s1 += v[j]; s2 += v[j] * v[j];
                }
#pragma unroll
                for (int off = 16; off; off >>= 1) {
                    s1 += __shfl_xor_sync(0xffffffffu, s1, off);
                    s2 += __shfl_xor_sync(0xffffffffu, s2, off);
                }
                float mean = s1 * (1.f / 160.f);
                float var = s2 * (1.f / 160.f) - mean * mean;
                float rstd = rsqrtf(var + EPSF);
#pragma unroll
                for (int j = 0; j < 5; j++) {
                    int c = lane + 32 * j;
                    sT[w * DM + c] = (v[j] - mean) * rstd * g1[c] + be1[c];
                }
                __syncwarp();
                float f[8];
#pragma unroll
                for (int j = 0; j < 8; j++) f[j] = 0.f;
                for (int k = 0; k < DM; k++) {
                    float a = sT[w * DM + k];
#pragma unroll
                    for (int j = 0; j < 8; j++)
                        f[j] += a * W1[k * 256 + lane + 32 * j];
                }
#pragma unroll
                for (int j = 0; j < 8; j++) {
                    int c = lane + 32 * j;
                    sF[w * 256 + c] = fmaxf(f[j] + bb1[c], 0.f);
                }
                __syncwarp();
#pragma unroll
                for (int j = 0; j < 5; j++) acc[j] = 0.f;
                for (int k = 0; k < 256; k++) {
                    float a = sF[w * 256 + k];
#pragma unroll
                    for (int j = 0; j < 5; j++)
                        acc[j] += a * W2[k * 160 + lane + 32 * j];
                }
                s1 = 0.f; s2 = 0.f;
#pragma unroll
                for (int j = 0; j < 5; j++) {
                    int c = lane + 32 * j;
                    v[j] = sT[w * DM + c] + acc[j] + bb2[c];
                    s1 += v[j]; s2 += v[j] * v[j];
                }
#pragma unroll
                for (int off = 16; off; off >>= 1) {
                    s1 += __shfl_xor_sync(0xffffffffu, s1, off);
                    s2 += __shfl_xor_sync(0xffffffffu, s2, off);
                }
                mean = s1 * (1.f / 160.f);
                var = s2 * (1.f / 160.f) - mean * mean;
                rstd = rsqrtf(var + EPSF);
#pragma unroll
                for (int j = 0; j < 5; j++) {
                    int c = lane + 32 * j;
                    float tn = (v[j] - mean) * rstd * g2v[c] + be2[c];
                    sT[w * DM + c] = tn;
                    g_t[r * DM + c] = tn;
                }
                __syncwarp();
                if (tl < 2) {
                    const float* Wq = aiw + (size_t)(tl + 1) * 76800;
                    const float* bq = aib + (tl + 1) * 480;
                    float q[15];
#pragma unroll
                    for (int j = 0; j < 15; j++) q[j] = 0.f;
                    for (int k = 0; k < DM; k++) {
                        float a = sT[w * DM + k];
#pragma unroll
                        for (int j = 0; j < 15; j++)
                            q[j] += a * Wq[k * 480 + lane + 32 * j];
                    }
#pragma unroll
                    for (int j = 0; j < 15; j++) {
                        int c = lane + 32 * j;
                        g_qkv[r * 480 + c] = q[j] + bq[c];
                    }
                } else {
                    if (lane < 3) {
                        float a = lb[lane];
                        for (int k = 0; k < DM; k++)
                            a += sT[w * DM + k] * lw[k * 3 + lane];
                        out[r * 3 + lane] = a;
                    }
                }
                __syncthreads();
            }
        }
        if (tl < 2) gbar();
    }
}

// ---------------- host ----------------
extern "C" void kernel_launch(void* const* d_in, const int* in_sizes, int n_in,
                              void* d_out, int out_size) {
    mega<<<NB, NT>>>(
        (const float*)d_in[0],  (const float*)d_in[1],  (const float*)d_in[2],
        (const float*)d_in[3],  (const float*)d_in[4],  (const float*)d_in[5],
        (const float*)d_in[6],  (const float*)d_in[7],  (const float*)d_in[8],
        (const float*)d_in[9],  (const float*)d_in[10], (const float*)d_in[11],
        (const float*)d_in[12], (const float*)d_in[13], (const float*)d_in[14],
        (const float*)d_in[15], (const float*)d_in[16], (const float*)d_in[17],
        (const float*)d_in[18], (const float*)d_in[19], (const float*)d_in[20],
        (const float*)d_in[21], (const float*)d_in[22], (const float*)d_in[23],
        (const float*)d_in[24], (const float*)d_in[25], (const float*)d_in[26],
        (const float*)d_in[27], (const int*)d_in[28],   (const int*)d_in[29],
        (float*)d_out);
}